// round 1
// baseline (speedup 1.0000x reference)
#include <cuda_runtime.h>

// S4D kernel: K[h,l] = 2 * Re( sum_n Cmod[h,n] * exp(dtA[h,n] * l) )
// H=1024, N=64, L=2048.
//
// Strategy: per (h,n), the real part r_l = Re(Cmod * exp(dtA*l)) sampled at
// stride 32 satisfies r_{k+2} = p*r_{k+1} + q*r_k with
//   w = exp(dtA*32), p = 2*Re(w), q = -|w|^2   (both roots |w|<1: stable).
// One warp per h. Lane owns l = lane + 32k, k = 0..L/32-1. 64 n-states per
// thread live in registers (ra/rb arrays, fully unrolled). 3 fma-pipe ops
// per (n,l). Coalesced stores.

#define H_ 1024
#define N_ 64

// Precomputed per (h,n) scratch (device globals: allocation-free).
__device__ float2 g_cm [H_ * N_];   // Cmod*? actually 2*Cmod (factor 2 folded)
__device__ float2 g_dta[H_ * N_];   // (dt*Re(A), dt*Im(A))
__device__ float2 g_w32[H_ * N_];   // exp(dtA*32)
__device__ float4 g_pq [H_ * N_ / 2]; // packed (p0,q0,p1,q1) for n, n+1

__global__ void s4d_precompute(const float* __restrict__ log_dt,
                               const float* __restrict__ C,
                               const float* __restrict__ A,
                               int total)
{
    int i = blockIdx.x * blockDim.x + threadIdx.x;
    if (i >= total) return;
    int h = i / N_;
    int n = i - h * N_;

    float dt  = expf(log_dt[h]);
    float ar  = A[2 * n];
    float ai  = A[2 * n + 1];
    float dre = dt * ar;
    float dim = dt * ai;

    // w1 = exp(dtA)
    float e1 = expf(dre);
    float s1, c1;
    sincosf(dim, &s1, &c1);
    float w1r = e1 * c1;
    float w1i = e1 * s1;

    // qd = (w1 - 1) / A   (complex divide)
    float den = ar * ar + ai * ai;
    float inv = 1.0f / den;
    float nr = w1r - 1.0f;
    float ni = w1i;
    float qdr = (nr * ar + ni * ai) * inv;
    float qdi = (ni * ar - nr * ai) * inv;

    // cm = 2 * C * qd
    float cr = C[2 * i];
    float ci = C[2 * i + 1];
    float cmr = 2.0f * (cr * qdr - ci * qdi);
    float cmi = 2.0f * (cr * qdi + ci * qdr);

    // w32 = exp(32 * dtA)
    float e32 = expf(32.0f * dre);
    float s32, c32;
    sincosf(32.0f * dim, &s32, &c32);
    float wr = e32 * c32;
    float wi = e32 * s32;

    g_cm[i]  = make_float2(cmr, cmi);
    g_dta[i] = make_float2(dre, dim);
    g_w32[i] = make_float2(wr, wi);

    // recurrence coeffs, packed pairwise as float4 (p0,q0,p1,q1)
    float p = 2.0f * wr;
    float q = -(wr * wr + wi * wi);
    ((float2*)g_pq)[i] = make_float2(p, q);
}

__global__ __launch_bounds__(32)
void s4d_main(float* __restrict__ out, int L)
{
    __shared__ float2 s_dta[N_];
    __shared__ float2 s_cm [N_];
    __shared__ float2 s_w32[N_];
    __shared__ float4 s_pq [N_ / 2];

    const int h    = blockIdx.x;
    const int lane = threadIdx.x;
    const int base = h * N_;

    for (int t = lane; t < N_; t += 32) {
        s_dta[t] = g_dta[base + t];
        s_cm [t] = g_cm [base + t];
        s_w32[t] = g_w32[base + t];
    }
    if (lane < N_ / 2) s_pq[lane] = g_pq[base / 2 + lane];
    __syncwarp();

    const float lf = (float)lane;

    float ra[N_];  // r_k   for each n
    float rb[N_];  // r_{k+1}

#pragma unroll
    for (int n = 0; n < N_; n++) {
        float2 d = s_dta[n];
        float ex = expf(d.x * lf);           // args small: lane <= 31
        float s, c;
        sincosf(d.y * lf, &s, &c);           // |arg| <= ~42 rad: fast path ok
        float er = ex * c;
        float ei = ex * s;
        float2 cm = s_cm[n];
        float zr = cm.x * er - cm.y * ei;    // z0 = cm * exp(dtA*lane)
        float zi = cm.x * ei + cm.y * er;
        ra[n] = zr;
        float2 w = s_w32[n];
        rb[n] = zr * w.x - zi * w.y;         // Re(z0 * w32) = r_1
    }

    float* orow = out + (size_t)h * L + lane;
    const int KT = L / 32;                   // 64

    for (int k = 0; k < KT; k += 2) {
        float a0 = 0.f, a1 = 0.f, a2 = 0.f, a3 = 0.f;
        float b0 = 0.f, b1 = 0.f, b2 = 0.f, b3 = 0.f;

#pragma unroll
        for (int n = 0; n < N_; n += 4) {
            float4 pq0 = s_pq[(n >> 1)];
            float4 pq1 = s_pq[(n >> 1) + 1];

            a0 += ra[n];
            b0 += rb[n];
            ra[n]   = fmaf(pq0.x, rb[n],   pq0.y * ra[n]);   // r_{k+2}
            rb[n]   = fmaf(pq0.x, ra[n],   pq0.y * rb[n]);   // r_{k+3}

            a1 += ra[n+1];
            b1 += rb[n+1];
            ra[n+1] = fmaf(pq0.z, rb[n+1], pq0.w * ra[n+1]);
            rb[n+1] = fmaf(pq0.z, ra[n+1], pq0.w * rb[n+1]);

            a2 += ra[n+2];
            b2 += rb[n+2];
            ra[n+2] = fmaf(pq1.x, rb[n+2], pq1.y * ra[n+2]);
            rb[n+2] = fmaf(pq1.x, ra[n+2], pq1.y * rb[n+2]);

            a3 += ra[n+3];
            b3 += rb[n+3];
            ra[n+3] = fmaf(pq1.z, rb[n+3], pq1.w * ra[n+3]);
            rb[n+3] = fmaf(pq1.z, ra[n+3], pq1.w * rb[n+3]);
        }

        float sa = (a0 + a1) + (a2 + a3);
        float sb = (b0 + b1) + (b2 + b3);
        orow[(size_t)k * 32]       = sa;
        orow[(size_t)(k + 1) * 32] = sb;
    }
}

extern "C" void kernel_launch(void* const* d_in, const int* in_sizes, int n_in,
                              void* d_out, int out_size)
{
    const float* log_dt = (const float*)d_in[0];
    const float* C      = (const float*)d_in[1];
    const float* A      = (const float*)d_in[2];
    // d_in[3] = input_length (int scalar); L derived from out_size instead.

    int H = in_sizes[0];           // 1024
    int L = out_size / H;          // 2048
    int total = H * N_;

    s4d_precompute<<<(total + 255) / 256, 256>>>(log_dt, C, A, total);
    s4d_main<<<H, 32>>>((float*)d_out, L);
}

// round 2
// speedup vs baseline: 1.6432x; 1.6432x over previous
#include <cuda_runtime.h>

// S4D kernel: K[h,l] = 2 * Re( sum_n Cmod[h,n] * exp(dtA[h,n] * l) ),
// H=1024, N=64, L=2048.
//
// Per (h,n): r_l = Re(Cmod * exp(dtA*l)) at l-stride 32 obeys
//   r_{k+2} = p*r_{k+1} + q*r_k,  w = exp(dtA*32), p = 2Re(w), q = -|w|^2
// (|roots| < 1: stable). One block (128 thr, 4 warps) per h. Lane owns
// l = lane + 32k. Warp w owns n in [16w, 16w+16) -> 16 states/thread,
// packed pairwise into f32x2 registers. Cross-warp reduction through
// double-buffered shared memory, 1 barrier per 2-k iteration.

#define N_     64
#define WARPS  4
#define NPW    (N_ / WARPS)    // 16 n per warp
#define NPAIR  (NPW / 2)       // 8 packed pairs per thread

typedef unsigned long long u64;

__device__ __forceinline__ u64 pack2(float lo, float hi) {
    u64 r; asm("mov.b64 %0, {%1,%2};" : "=l"(r) : "f"(lo), "f"(hi)); return r;
}
__device__ __forceinline__ void unpack2(u64 v, float& lo, float& hi) {
    asm("mov.b64 {%0,%1}, %2;" : "=f"(lo), "=f"(hi) : "l"(v));
}
__device__ __forceinline__ u64 fma2(u64 a, u64 b, u64 c) {
    u64 d; asm("fma.rn.f32x2 %0,%1,%2,%3;" : "=l"(d) : "l"(a), "l"(b), "l"(c)); return d;
}
__device__ __forceinline__ u64 mul2(u64 a, u64 b) {
    u64 d; asm("mul.rn.f32x2 %0,%1,%2;" : "=l"(d) : "l"(a), "l"(b)); return d;
}
__device__ __forceinline__ u64 add2(u64 a, u64 b) {
    u64 d; asm("add.rn.f32x2 %0,%1,%2;" : "=l"(d) : "l"(a), "l"(b)); return d;
}

__global__ __launch_bounds__(128)
void s4d_fused(const float* __restrict__ log_dt,
               const float* __restrict__ C,
               const float* __restrict__ A,
               float* __restrict__ out, int L)
{
    __shared__ float2 s_dta[N_], s_cm[N_], s_w32[N_], s_pq[N_];
    __shared__ float2 s_red[2][WARPS][32];   // (sa, sb) partials, double-buffered

    const int h    = blockIdx.x;
    const int tid  = threadIdx.x;
    const int wid  = tid >> 5;
    const int lane = tid & 31;

    // ---- per-n parameter precompute (threads 0..63, one n each) ----
    if (tid < N_) {
        int n = tid;
        float dt  = expf(log_dt[h]);
        float ar  = A[2 * n], ai = A[2 * n + 1];
        float dre = dt * ar, dim = dt * ai;

        float e1 = expf(dre); float s1, c1; sincosf(dim, &s1, &c1);
        float w1r = e1 * c1, w1i = e1 * s1;

        float inv = 1.0f / (ar * ar + ai * ai);
        float nr = w1r - 1.0f, ni = w1i;
        float qdr = (nr * ar + ni * ai) * inv;
        float qdi = (ni * ar - nr * ai) * inv;

        float cr = C[2 * (h * N_ + n)], ci = C[2 * (h * N_ + n) + 1];
        float cmr = 2.0f * (cr * qdr - ci * qdi);
        float cmi = 2.0f * (cr * qdi + ci * qdr);

        float e32 = expf(32.0f * dre); float s32, c32; sincosf(32.0f * dim, &s32, &c32);
        float wr = e32 * c32, wi = e32 * s32;

        s_dta[n] = make_float2(dre, dim);
        s_cm [n] = make_float2(cmr, cmi);
        s_w32[n] = make_float2(wr, wi);
        s_pq [n] = make_float2(2.0f * wr, -(wr * wr + wi * wi));
    }
    __syncthreads();

    // ---- per-thread state init: z0 = cm * exp(dtA * lane), r0 = Re(z0),
    //      r1 = Re(z0 * w32) ----
    const float lf = (float)lane;
    const int   n0 = wid * NPW;

    u64 ra[NPAIR], rb[NPAIR], p2[NPAIR], q2[NPAIR];
#pragma unroll
    for (int j = 0; j < NPAIR; j++) {
        float z0[2], z1[2];
#pragma unroll
        for (int t = 0; t < 2; t++) {
            int n = n0 + 2 * j + t;
            float2 d = s_dta[n];
            float ex = expf(d.x * lf);
            float s, c; sincosf(d.y * lf, &s, &c);
            float er = ex * c, ei = ex * s;
            float2 cm = s_cm[n];
            float zr = cm.x * er - cm.y * ei;
            float zi = cm.x * ei + cm.y * er;
            float2 w = s_w32[n];
            z0[t] = zr;
            z1[t] = zr * w.x - zi * w.y;
        }
        ra[j] = pack2(z0[0], z0[1]);
        rb[j] = pack2(z1[0], z1[1]);
        float2 pqa = s_pq[n0 + 2 * j];
        float2 pqb = s_pq[n0 + 2 * j + 1];
        p2[j] = pack2(pqa.x, pqb.x);
        q2[j] = pack2(pqa.y, pqb.y);
    }

    float* orow   = out + (size_t)h * L;
    const int KT  = L / 32;         // 64 k-steps, processed 2 per iteration
    int parity    = 0;

#pragma unroll 1
    for (int k = 0; k < KT; k += 2) {
        u64 a0 = 0ull, a1 = 0ull, b0 = 0ull, b1 = 0ull;  // 0ull == packed (+0,+0)
#pragma unroll
        for (int j = 0; j < NPAIR; j++) {
            if (j & 1) {
                a1 = add2(a1, ra[j]);
                ra[j] = fma2(p2[j], rb[j], mul2(q2[j], ra[j]));
                b1 = add2(b1, rb[j]);
                rb[j] = fma2(p2[j], ra[j], mul2(q2[j], rb[j]));
            } else {
                a0 = add2(a0, ra[j]);
                ra[j] = fma2(p2[j], rb[j], mul2(q2[j], ra[j]));
                b0 = add2(b0, rb[j]);
                rb[j] = fma2(p2[j], ra[j], mul2(q2[j], rb[j]));
            }
        }
        u64 aa = add2(a0, a1), bb = add2(b0, b1);
        float al, ah, bl, bh;
        unpack2(aa, al, ah); unpack2(bb, bl, bh);
        s_red[parity][wid][lane] = make_float2(al + ah, bl + bh);
        __syncthreads();

        // Reduce across the 4 warps. Rotate which warp-pair does it (parity)
        // to balance issue load. Warp rbase handles k (x component), warp
        // rbase+1 handles k+1 (y component).
        int rbase = parity ? 2 : 0;
        if (wid == rbase || wid == rbase + 1) {
            int kk = wid - rbase;            // 0 -> k, 1 -> k+1
            float2 v0 = s_red[parity][0][lane];
            float2 v1 = s_red[parity][1][lane];
            float2 v2 = s_red[parity][2][lane];
            float2 v3 = s_red[parity][3][lane];
            float r = kk ? ((v0.y + v1.y) + (v2.y + v3.y))
                         : ((v0.x + v1.x) + (v2.x + v3.x));
            orow[(size_t)(k + kk) * 32 + lane] = r;
        }
        parity ^= 1;
    }
}

extern "C" void kernel_launch(void* const* d_in, const int* in_sizes, int n_in,
                              void* d_out, int out_size)
{
    const float* log_dt = (const float*)d_in[0];
    const float* C      = (const float*)d_in[1];
    const float* A      = (const float*)d_in[2];
    // d_in[3] = input_length scalar; L derived from out_size.

    int H = in_sizes[0];          // 1024
    int L = out_size / H;         // 2048

    s4d_fused<<<H, 128>>>(log_dt, C, A, (float*)d_out, L);
}

// round 3
// speedup vs baseline: 2.0821x; 1.2670x over previous
#include <cuda_runtime.h>

// S4D kernel: K[h,l] = 2 * Re( sum_n Cmod[h,n] * exp(dtA[h,n] * l) ),
// H=1024, N=64, L=2048.
//
// Per (h,n): r_l = Re(Cmod * exp(dtA*l)) at l-stride 32 obeys
//   r_{k+2} = p*r_{k+1} + q*r_k,  w = exp(dtA*32), p = 2Re(w), q = -|w|^2
// (|roots| < 1: stable). One block (128 thr, 4 warps) per h. Lane owns
// l = lane + 32k. Warp w owns n in [16w, 16w+16) -> 8 packed f32x2 states
// per thread. NO barriers in the main loop: per-iteration partials go to a
// 32KB shared buffer; a single __syncthreads precedes one final cross-warp
// reduction pass with coalesced stores.

#define N_     64
#define WARPS  4
#define NPW    (N_ / WARPS)    // 16 n per warp
#define NPAIR  (NPW / 2)       // 8 packed pairs per thread
#define ITERS  32              // KT/2, KT = L/32 = 64

typedef unsigned long long u64;

__device__ __forceinline__ u64 pack2(float lo, float hi) {
    u64 r; asm("mov.b64 %0, {%1,%2};" : "=l"(r) : "f"(lo), "f"(hi)); return r;
}
__device__ __forceinline__ void unpack2(u64 v, float& lo, float& hi) {
    asm("mov.b64 {%0,%1}, %2;" : "=f"(lo), "=f"(hi) : "l"(v));
}
__device__ __forceinline__ u64 fma2(u64 a, u64 b, u64 c) {
    u64 d; asm("fma.rn.f32x2 %0,%1,%2,%3;" : "=l"(d) : "l"(a), "l"(b), "l"(c)); return d;
}
__device__ __forceinline__ u64 mul2(u64 a, u64 b) {
    u64 d; asm("mul.rn.f32x2 %0,%1,%2;" : "=l"(d) : "l"(a), "l"(b)); return d;
}
__device__ __forceinline__ u64 add2(u64 a, u64 b) {
    u64 d; asm("add.rn.f32x2 %0,%1,%2;" : "=l"(d) : "l"(a), "l"(b)); return d;
}

__global__ __launch_bounds__(128, 5)
void s4d_fused(const float* __restrict__ log_dt,
               const float* __restrict__ C,
               const float* __restrict__ A,
               float* __restrict__ out, int L)
{
    __shared__ float2 s_dta[N_], s_cm[N_], s_w32[N_], s_pq[N_];
    __shared__ float2 s_part[ITERS][WARPS][32];   // per-iteration partials

    const int h    = blockIdx.x;
    const int tid  = threadIdx.x;
    const int wid  = tid >> 5;
    const int lane = tid & 31;

    // ---- per-n parameter precompute (threads 0..63, one n each) ----
    if (tid < N_) {
        int n = tid;
        float dt  = expf(log_dt[h]);
        float ar  = A[2 * n], ai = A[2 * n + 1];
        float dre = dt * ar, dim = dt * ai;

        float e1 = expf(dre); float s1, c1; sincosf(dim, &s1, &c1);
        float w1r = e1 * c1, w1i = e1 * s1;

        float inv = 1.0f / (ar * ar + ai * ai);
        float nr = w1r - 1.0f, ni = w1i;
        float qdr = (nr * ar + ni * ai) * inv;
        float qdi = (ni * ar - nr * ai) * inv;

        float cr = C[2 * (h * N_ + n)], ci = C[2 * (h * N_ + n) + 1];
        float cmr = 2.0f * (cr * qdr - ci * qdi);
        float cmi = 2.0f * (cr * qdi + ci * qdr);

        float e32 = expf(32.0f * dre); float s32, c32; sincosf(32.0f * dim, &s32, &c32);
        float wr = e32 * c32, wi = e32 * s32;

        s_dta[n] = make_float2(dre, dim);
        s_cm [n] = make_float2(cmr, cmi);
        s_w32[n] = make_float2(wr, wi);
        s_pq [n] = make_float2(2.0f * wr, -(wr * wr + wi * wi));
    }
    __syncthreads();

    // ---- per-thread state init: z0 = cm * exp(dtA * lane),
    //      ra = Re(z0), rb = Re(z0 * w32) ----
    const float lf = (float)lane;
    const int   n0 = wid * NPW;

    u64 ra[NPAIR], rb[NPAIR], p2[NPAIR], q2[NPAIR];
#pragma unroll
    for (int j = 0; j < NPAIR; j++) {
        float z0[2], z1[2];
#pragma unroll
        for (int t = 0; t < 2; t++) {
            int n = n0 + 2 * j + t;
            float2 d = s_dta[n];
            float ex = expf(d.x * lf);
            float s, c; sincosf(d.y * lf, &s, &c);
            float er = ex * c, ei = ex * s;
            float2 cm = s_cm[n];
            float zr = cm.x * er - cm.y * ei;
            float zi = cm.x * ei + cm.y * er;
            float2 w = s_w32[n];
            z0[t] = zr;
            z1[t] = zr * w.x - zi * w.y;
        }
        ra[j] = pack2(z0[0], z0[1]);
        rb[j] = pack2(z1[0], z1[1]);
        float2 pqa = s_pq[n0 + 2 * j];
        float2 pqb = s_pq[n0 + 2 * j + 1];
        p2[j] = pack2(pqa.x, pqb.x);
        q2[j] = pack2(pqa.y, pqb.y);
    }

    // ---- main loop: no barriers; partials to shared ----
    float2* s_row = &s_part[0][wid][lane];
#pragma unroll 2
    for (int it = 0; it < ITERS; it++) {
        u64 a0 = 0ull, a1 = 0ull, b0 = 0ull, b1 = 0ull;
#pragma unroll
        for (int j = 0; j < NPAIR; j++) {
            if (j & 1) {
                a1 = add2(a1, ra[j]);
                ra[j] = fma2(p2[j], rb[j], mul2(q2[j], ra[j]));
                b1 = add2(b1, rb[j]);
                rb[j] = fma2(p2[j], ra[j], mul2(q2[j], rb[j]));
            } else {
                a0 = add2(a0, ra[j]);
                ra[j] = fma2(p2[j], rb[j], mul2(q2[j], ra[j]));
                b0 = add2(b0, rb[j]);
                rb[j] = fma2(p2[j], ra[j], mul2(q2[j], rb[j]));
            }
        }
        u64 aa = add2(a0, a1), bb = add2(b0, b1);
        float al, ah, bl, bh;
        unpack2(aa, al, ah); unpack2(bb, bl, bh);
        s_row[(size_t)it * (WARPS * 32)] = make_float2(al + ah, bl + bh);
    }
    __syncthreads();

    // ---- final cross-warp reduction: warp w handles k = w + 4i ----
    float* orow = out + (size_t)h * L;
#pragma unroll
    for (int i = 0; i < 16; i++) {
        int k  = wid + 4 * i;
        int it = k >> 1;
        float2 v0 = s_part[it][0][lane];
        float2 v1 = s_part[it][1][lane];
        float2 v2 = s_part[it][2][lane];
        float2 v3 = s_part[it][3][lane];
        float r = (wid & 1) ? ((v0.y + v1.y) + (v2.y + v3.y))
                            : ((v0.x + v1.x) + (v2.x + v3.x));
        orow[(size_t)k * 32 + lane] = r;
    }
}

extern "C" void kernel_launch(void* const* d_in, const int* in_sizes, int n_in,
                              void* d_out, int out_size)
{
    const float* log_dt = (const float*)d_in[0];
    const float* C      = (const float*)d_in[1];
    const float* A      = (const float*)d_in[2];
    // d_in[3] = input_length scalar; L derived from out_size.

    int H = in_sizes[0];          // 1024
    int L = out_size / H;         // 2048

    s4d_fused<<<H, 128>>>(log_dt, C, A, (float*)d_out, L);
}